// round 2
// baseline (speedup 1.0000x reference)
#include <cuda_runtime.h>

#define NIMG 32
#define CDIM 512
#define TLEN 1024
#define NROWS (NIMG * TLEN)   // 32768
#define NB    2048

// Output layout (float32, concatenated in return order):
//   [0)                 x_d_out        : 32*512*1024 = 16777216
//   [16777216)          commit_loss    : 1
//   [16777217)          perplexity     : 1
//   [16777218)          new_codebook   : 2048*512 = 1048576
//   [17825794)          code_sum_ema   : 1048576
//   [18874370)          code_count_ema : 2048
#define OFF_LOSS  16777216
#define OFF_PERP  16777217
#define OFF_NCB   16777218
#define OFF_SUM   (OFF_NCB + NB * CDIM)
#define OFF_CNT   (OFF_SUM + NB * CDIM)

__device__ unsigned long long g_best[NROWS];
__device__ float g_cnorm[NB];
__device__ double g_loss;

__device__ __forceinline__ unsigned long long packKey(float s, unsigned j) {
    unsigned u = __float_as_uint(s);
    u = (u & 0x80000000u) ? ~u : (u | 0x80000000u);   // order-preserving map
    return ((unsigned long long)u << 32) | j;
}

// ---------------------------------------------------------------------------
// 1) init scratch (uses d_out's code_sum / code_count regions as accumulators)
// ---------------------------------------------------------------------------
__global__ void k_init(float* __restrict__ sumR, float* __restrict__ cntR) {
    int i = blockIdx.x * 256 + threadIdx.x;           // grid covers NB*CDIM
    sumR[i] = 0.0f;
    if (i < NROWS) g_best[i] = 0xFFFFFFFFFFFFFFFFull;
    if (i < NB)    cntR[i]   = 0.0f;
    if (i == 0)    g_loss    = 0.0;
}

// ---------------------------------------------------------------------------
// 2) codebook row norms
// ---------------------------------------------------------------------------
__global__ void k_cnorm(const float* __restrict__ cb) {
    int warp = blockIdx.x * 8 + (threadIdx.x >> 5);   // 256 blocks * 8 warps = 2048
    int lane = threadIdx.x & 31;
    const float* row = cb + (size_t)warp * CDIM;
    float s = 0.0f;
#pragma unroll
    for (int i = 0; i < CDIM / 32; i++) {
        float v = row[lane + i * 32];
        s += v * v;
    }
#pragma unroll
    for (int o = 16; o > 0; o >>= 1) s += __shfl_xor_sync(0xFFFFFFFFu, s, o);
    if (lane == 0) g_cnorm[warp] = s;
}

// ---------------------------------------------------------------------------
// 3) fused fp32 GEMM (x_flat @ cb^T) + per-row argmin of  ||c||^2 - 2 x.c
//    block tile 128(M=t) x 128(N=codes) x 16(K), 256 threads, 8x8 per thread
// ---------------------------------------------------------------------------
__global__ __launch_bounds__(256, 2)
void k_argmin(const float* __restrict__ x, const float* __restrict__ cb) {
    __shared__ float As[16 * 128];
    __shared__ float Bs[16 * 128];
    __shared__ unsigned long long red[128 * 17];      // stride 17: kill bank conflicts

    const int tid = threadIdx.x;
    const int tx = tid & 15, ty = tid >> 4;
    const int m0 = blockIdx.y * 128;                  // row tile (t-contiguous)
    const int j0 = blockIdx.x * 128;                  // code tile
    // x_flat[m0+t][k] = x[img][k][t0+t]  (contiguous in t)
    const float* xbase = x + (size_t)(m0 >> 10) * (CDIM * TLEN) + (m0 & 1023);

    float acc[8][8];
#pragma unroll
    for (int r = 0; r < 8; r++)
#pragma unroll
        for (int c = 0; c < 8; c++) acc[r][c] = 0.0f;

    for (int kt = 0; kt < CDIM; kt += 16) {
        // A tile: 16k x 128t, float4 coalesced along t
#pragma unroll
        for (int s = 0; s < 2; s++) {
            int v = tid + s * 256;                    // 512 float4s
            int k = v >> 5, t4 = (v & 31) << 2;
            float4 g = *(const float4*)(xbase + (size_t)(kt + k) * TLEN + t4);
            *(float4*)&As[k * 128 + t4] = g;
        }
        // B tile: cb rows, stored transposed Bs[k][j]
#pragma unroll
        for (int s = 0; s < 2; s++) {
            int v = tid + s * 256;
            int j = v >> 2, k4 = (v & 3) << 2;
            float4 g = *(const float4*)(cb + (size_t)(j0 + j) * CDIM + kt + k4);
            Bs[(k4 + 0) * 128 + j] = g.x;
            Bs[(k4 + 1) * 128 + j] = g.y;
            Bs[(k4 + 2) * 128 + j] = g.z;
            Bs[(k4 + 3) * 128 + j] = g.w;
        }
        __syncthreads();
#pragma unroll
        for (int kk = 0; kk < 16; kk++) {
            float a[8], b[8];
            *(float4*)(a)     = *(float4*)&As[kk * 128 + ty * 8];
            *(float4*)(a + 4) = *(float4*)&As[kk * 128 + ty * 8 + 4];
            *(float4*)(b)     = *(float4*)&Bs[kk * 128 + tx * 8];
            *(float4*)(b + 4) = *(float4*)&Bs[kk * 128 + tx * 8 + 4];
#pragma unroll
            for (int r = 0; r < 8; r++)
#pragma unroll
                for (int c = 0; c < 8; c++) acc[r][c] += a[r] * b[c];
        }
        __syncthreads();
    }

    // per-thread argmin over its 8 cols, per row
#pragma unroll
    for (int r = 0; r < 8; r++) {
        unsigned long long key = 0xFFFFFFFFFFFFFFFFull;
#pragma unroll
        for (int c = 0; c < 8; c++) {
            int j = j0 + tx * 8 + c;
            float s = g_cnorm[j] - 2.0f * acc[r][c];
            unsigned long long k2 = packKey(s, (unsigned)j);
            if (k2 < key) key = k2;
        }
        red[(ty * 8 + r) * 17 + tx] = key;
    }
    __syncthreads();
    if (tid < 128) {
        unsigned long long m = red[tid * 17];
#pragma unroll
        for (int i = 1; i < 16; i++) {
            unsigned long long v = red[tid * 17 + i];
            if (v < m) m = v;
        }
        atomicMin(&g_best[m0 + tid], m);
    }
}

// ---------------------------------------------------------------------------
// 4) gather codebook -> x_d_out (transposed layout), segment sums + counts,
//    commit loss.  Block = 32 t-values of one image, 256 threads (8 c-slices).
// ---------------------------------------------------------------------------
__global__ void k_scatter(const float* __restrict__ x, const float* __restrict__ cb,
                          float* __restrict__ out, float* __restrict__ sumR,
                          float* __restrict__ cntR) {
    __shared__ int sidx[32];
    __shared__ float lred[256];
    const int tid = threadIdx.x;
    const int r0 = blockIdx.x * 32;
    const int img = r0 >> 10, t0 = r0 & 1023;

    if (tid < 32) {
        int idx = (int)(g_best[r0 + tid] & 0xFFFFFFFFu);
        sidx[tid] = idx;
        atomicAdd(&cntR[idx], 1.0f);
    }
    __syncthreads();

    const int tt = tid & 31;
    const int c0 = tid >> 5;
    const int idx = sidx[tt];
    const float* cbrow = cb + (size_t)idx * CDIM;
    float loss = 0.0f;
#pragma unroll
    for (int c = c0; c < CDIM; c += 8) {
        float cv = cbrow[c];
        size_t xoff = ((size_t)img * CDIM + c) * TLEN + t0 + tt;
        float xv = x[xoff];
        out[xoff] = cv;                                    // x_d_out
        atomicAdd(&sumR[(size_t)idx * CDIM + c], xv);      // segment sum
        float d = xv - cv;
        loss += d * d;
    }
    lred[tid] = loss;
    __syncthreads();
    for (int o = 128; o > 0; o >>= 1) {
        if (tid < o) lred[tid] += lred[tid + o];
        __syncthreads();
    }
    if (tid == 0) atomicAdd(&g_loss, (double)lred[0]);
}

// ---------------------------------------------------------------------------
// 5) perplexity from RAW counts (sum of counts is exactly NROWS) + commit loss
// ---------------------------------------------------------------------------
__global__ void k_perp(float* __restrict__ out, const float* __restrict__ cntR) {
    __shared__ double sred[256];
    const int tid = threadIdx.x;
    double s = 0.0;
    for (int j = tid; j < NB; j += 256) {
        float cnt = cntR[j];
        float prob = cnt / (32768.0f + 1e-10f);
        s += (double)(prob * logf(prob + 1e-7f));
    }
    sred[tid] = s;
    __syncthreads();
    for (int o = 128; o > 0; o >>= 1) {
        if (tid < o) sred[tid] += sred[tid + o];
        __syncthreads();
    }
    if (tid == 0) {
        out[OFF_PERP] = (float)exp(-sred[0]);
        out[OFF_LOSS] = (float)(g_loss / (double)((size_t)NROWS * CDIM));
    }
}

// ---------------------------------------------------------------------------
// 6) EMA updates + codebook reset (in-place transform of sum/count regions)
// ---------------------------------------------------------------------------
__global__ void k_final(const float* __restrict__ x, const float* __restrict__ cs_in,
                        const float* __restrict__ cc_in, float* __restrict__ sumR,
                        float* __restrict__ cntR, float* __restrict__ ncb) {
    const int j = blockIdx.x;
    const int tid = threadIdx.x;
    float cnt = cntR[j];                          // raw count
    __syncthreads();                              // all reads before thread0 write
    float cema = 0.99f * cc_in[j] + 0.01f * cnt;
    bool usage = (cema >= 1.0f);
    float denom = fmaxf(cema, 1e-10f);
    const int jimg = j >> 10, jt = j & 1023;
    for (int c = tid; c < CDIM; c += 256) {
        float ns = sumR[(size_t)j * CDIM + c];
        float sema = 0.99f * cs_in[(size_t)j * CDIM + c] + 0.01f * ns;
        sumR[(size_t)j * CDIM + c] = sema;        // code_sum_ema out
        float upd = sema / denom;
        // reset path uses x_flat[j] = x[jimg][c][jt]
        float rnd = x[((size_t)jimg * CDIM + c) * TLEN + jt];
        ncb[(size_t)j * CDIM + c] = usage ? upd : rnd;
    }
    if (tid == 0) cntR[j] = cema;                 // code_count_ema out
}

// ---------------------------------------------------------------------------
extern "C" void kernel_launch(void* const* d_in, const int* in_sizes, int n_in,
                              void* d_out, int out_size) {
    const float* x  = (const float*)d_in[0];
    const float* cb = (const float*)d_in[1];
    const float* cs = (const float*)d_in[2];
    const float* cc = (const float*)d_in[3];
    float* out  = (float*)d_out;
    float* ncb  = out + OFF_NCB;
    float* sumR = out + OFF_SUM;
    float* cntR = out + OFF_CNT;

    k_init<<<(NB * CDIM) / 256, 256>>>(sumR, cntR);
    k_cnorm<<<NB / 8, 256>>>(cb);
    dim3 g(NB / 128, NROWS / 128);                // (16, 256)
    k_argmin<<<g, 256>>>(x, cb);
    k_scatter<<<NROWS / 32, 256>>>(x, cb, out, sumR, cntR);
    k_perp<<<1, 256>>>(out, cntR);
    k_final<<<NB, 256>>>(x, cs, cc, sumR, cntR, ncb);
}

// round 4
// speedup vs baseline: 1.5357x; 1.5357x over previous
#include <cuda_runtime.h>

#define NIMG 32
#define CDIM 512
#define TLEN 1024
#define NROWS (NIMG * TLEN)   // 32768
#define NB    2048

#define OFF_LOSS  16777216
#define OFF_PERP  16777217
#define OFF_NCB   16777218
#define OFF_SUM   (OFF_NCB + NB * CDIM)
#define OFF_CNT   (OFF_SUM + NB * CDIM)

__device__ unsigned long long g_best[NROWS];
__device__ float g_cnorm[NB];
__device__ double g_loss;

__device__ __forceinline__ unsigned long long packKey(float s, unsigned j) {
    unsigned u = __float_as_uint(s);
    u = (u & 0x80000000u) ? ~u : (u | 0x80000000u);   // order-preserving map
    return ((unsigned long long)u << 32) | j;
}

// ---------------------------------------------------------------------------
// 1) init scratch (uses d_out's code_sum / code_count regions as accumulators)
// ---------------------------------------------------------------------------
__global__ void k_init(float* __restrict__ sumR, float* __restrict__ cntR) {
    int i = blockIdx.x * 256 + threadIdx.x;           // grid covers NB*CDIM
    sumR[i] = 0.0f;
    if (i < NROWS) g_best[i] = 0xFFFFFFFFFFFFFFFFull;
    if (i < NB)    cntR[i]   = 0.0f;
    if (i == 0)    g_loss    = 0.0;
}

// ---------------------------------------------------------------------------
// 2) codebook row norms
// ---------------------------------------------------------------------------
__global__ void k_cnorm(const float* __restrict__ cb) {
    int warp = blockIdx.x * 8 + (threadIdx.x >> 5);
    int lane = threadIdx.x & 31;
    const float* row = cb + (size_t)warp * CDIM;
    float s = 0.0f;
#pragma unroll
    for (int i = 0; i < CDIM / 32; i++) {
        float v = row[lane + i * 32];
        s += v * v;
    }
#pragma unroll
    for (int o = 16; o > 0; o >>= 1) s += __shfl_xor_sync(0xFFFFFFFFu, s, o);
    if (lane == 0) g_cnorm[warp] = s;
}

// ---------------------------------------------------------------------------
// 3) fused fp32 GEMM (x_flat @ cb^T) + per-row argmin, using packed
//    fma.rn.f32x2 (FFMA2): accumulators paired along the ROW dim so A pairs
//    come free from the float4 shared loads; B is broadcast-packed.
//    block tile 128(M) x 128(N) x 16(K), 256 threads, 8x8 per thread.
// ---------------------------------------------------------------------------
__global__ __launch_bounds__(256, 2)
void k_argmin(const float* __restrict__ x, const float* __restrict__ cb) {
    __shared__ float As[16 * 128];
    __shared__ float Bs[16 * 128];
    __shared__ unsigned long long red[128 * 17];

    const int tid = threadIdx.x;
    const int tx = tid & 15, ty = tid >> 4;
    const int m0 = blockIdx.y * 128;
    const int j0 = blockIdx.x * 128;
    const float* xbase = x + (size_t)(m0 >> 10) * (CDIM * TLEN) + (m0 & 1023);

    // acc2[rp][c] holds rows (2rp, 2rp+1) x col c as packed f32x2
    unsigned long long acc2[4][8];
#pragma unroll
    for (int rp = 0; rp < 4; rp++)
#pragma unroll
        for (int c = 0; c < 8; c++) acc2[rp][c] = 0ull;

    for (int kt = 0; kt < CDIM; kt += 16) {
#pragma unroll
        for (int s = 0; s < 2; s++) {
            int v = tid + s * 256;
            int k = v >> 5, t4 = (v & 31) << 2;
            float4 g = *(const float4*)(xbase + (size_t)(kt + k) * TLEN + t4);
            *(float4*)&As[k * 128 + t4] = g;
        }
#pragma unroll
        for (int s = 0; s < 2; s++) {
            int v = tid + s * 256;
            int j = v >> 2, k4 = (v & 3) << 2;
            float4 g = *(const float4*)(cb + (size_t)(j0 + j) * CDIM + kt + k4);
            Bs[(k4 + 0) * 128 + j] = g.x;
            Bs[(k4 + 1) * 128 + j] = g.y;
            Bs[(k4 + 2) * 128 + j] = g.z;
            Bs[(k4 + 3) * 128 + j] = g.w;
        }
        __syncthreads();
#pragma unroll
        for (int kk = 0; kk < 16; kk++) {
            // A pairs: rows (2rp,2rp+1) already adjacent in shared -> u64 pairs
            ulonglong2 alo = *(const ulonglong2*)&As[kk * 128 + ty * 8];
            ulonglong2 ahi = *(const ulonglong2*)&As[kk * 128 + ty * 8 + 4];
            unsigned long long a2[4] = {alo.x, alo.y, ahi.x, ahi.y};
            float4 b0 = *(const float4*)&Bs[kk * 128 + tx * 8];
            float4 b1 = *(const float4*)&Bs[kk * 128 + tx * 8 + 4];
            float bf[8] = {b0.x, b0.y, b0.z, b0.w, b1.x, b1.y, b1.z, b1.w};
            unsigned long long b2[8];
#pragma unroll
            for (int c = 0; c < 8; c++) {
                unsigned bu = __float_as_uint(bf[c]);
                asm("mov.b64 %0, {%1, %1};" : "=l"(b2[c]) : "r"(bu));
            }
#pragma unroll
            for (int c = 0; c < 8; c++)
#pragma unroll
                for (int rp = 0; rp < 4; rp++)
                    asm("fma.rn.f32x2 %0, %1, %2, %0;"
                        : "+l"(acc2[rp][c]) : "l"(a2[rp]), "l"(b2[c]));
        }
        __syncthreads();
    }

    // unpack + per-thread argmin over its 8 cols, per row
#pragma unroll
    for (int rp = 0; rp < 4; rp++) {
        unsigned long long keyLo = 0xFFFFFFFFFFFFFFFFull;
        unsigned long long keyHi = 0xFFFFFFFFFFFFFFFFull;
#pragma unroll
        for (int c = 0; c < 8; c++) {
            int j = j0 + tx * 8 + c;
            unsigned lo, hi;
            asm("mov.b64 {%0, %1}, %2;" : "=r"(lo), "=r"(hi) : "l"(acc2[rp][c]));
            float s0 = g_cnorm[j] - 2.0f * __uint_as_float(lo);
            float s1 = g_cnorm[j] - 2.0f * __uint_as_float(hi);
            unsigned long long k0 = packKey(s0, (unsigned)j);
            unsigned long long k1 = packKey(s1, (unsigned)j);
            if (k0 < keyLo) keyLo = k0;
            if (k1 < keyHi) keyHi = k1;
        }
        red[(ty * 8 + 2 * rp)     * 17 + tx] = keyLo;
        red[(ty * 8 + 2 * rp + 1) * 17 + tx] = keyHi;
    }
    __syncthreads();
    if (tid < 128) {
        unsigned long long m = red[tid * 17];
#pragma unroll
        for (int i = 1; i < 16; i++) {
            unsigned long long v = red[tid * 17 + i];
            if (v < m) m = v;
        }
        atomicMin(&g_best[m0 + tid], m);
    }
}

// ---------------------------------------------------------------------------
// 4) gather codebook -> x_d_out, segment sums + counts, commit loss.
//    Grid: (NROWS/32, 4 c-tiles). Block = 32 t-values x 8 c-slices of a
//    128-wide c-tile; each thread does 16 strided c iterations.
// ---------------------------------------------------------------------------
__global__ void k_scatter(const float* __restrict__ x, const float* __restrict__ cb,
                          float* __restrict__ out, float* __restrict__ sumR,
                          float* __restrict__ cntR) {
    __shared__ int sidx[32];
    __shared__ float lred[256];
    const int tid = threadIdx.x;
    const int r0 = blockIdx.x * 32;
    const int cbase = blockIdx.y * 128;               // c-tile of width 128
    const int img = r0 >> 10, t0 = r0 & 1023;

    if (tid < 32) {
        int idx = (int)(g_best[r0 + tid] & 0xFFFFFFFFu);
        sidx[tid] = idx;
        if (blockIdx.y == 0) atomicAdd(&cntR[idx], 1.0f);
    }
    __syncthreads();

    const int tt = tid & 31;
    const int c0 = cbase + (tid >> 5);
    const int idx = sidx[tt];
    const float* cbrow = cb + (size_t)idx * CDIM;
    float loss = 0.0f;
#pragma unroll
    for (int ci = 0; ci < 16; ci++) {
        int c = c0 + ci * 8;
        float cv = cbrow[c];
        size_t xoff = ((size_t)img * CDIM + c) * TLEN + t0 + tt;
        float xv = x[xoff];
        out[xoff] = cv;                                    // x_d_out
        atomicAdd(&sumR[(size_t)idx * CDIM + c], xv);      // segment sum
        float d = xv - cv;
        loss += d * d;
    }
    lred[tid] = loss;
    __syncthreads();
    for (int o = 128; o > 0; o >>= 1) {
        if (tid < o) lred[tid] += lred[tid + o];
        __syncthreads();
    }
    if (tid == 0) atomicAdd(&g_loss, (double)lred[0]);
}

// ---------------------------------------------------------------------------
// 5) perplexity from RAW counts + commit loss
// ---------------------------------------------------------------------------
__global__ void k_perp(float* __restrict__ out, const float* __restrict__ cntR) {
    __shared__ double sred[256];
    const int tid = threadIdx.x;
    double s = 0.0;
    for (int j = tid; j < NB; j += 256) {
        float cnt = cntR[j];
        float prob = cnt / (32768.0f + 1e-10f);
        s += (double)(prob * logf(prob + 1e-7f));
    }
    sred[tid] = s;
    __syncthreads();
    for (int o = 128; o > 0; o >>= 1) {
        if (tid < o) sred[tid] += sred[tid + o];
        __syncthreads();
    }
    if (tid == 0) {
        out[OFF_PERP] = (float)exp(-sred[0]);
        out[OFF_LOSS] = (float)(g_loss / (double)((size_t)NROWS * CDIM));
    }
}

// ---------------------------------------------------------------------------
// 6) EMA updates + codebook reset
// ---------------------------------------------------------------------------
__global__ void k_final(const float* __restrict__ x, const float* __restrict__ cs_in,
                        const float* __restrict__ cc_in, float* __restrict__ sumR,
                        float* __restrict__ cntR, float* __restrict__ ncb) {
    const int j = blockIdx.x;
    const int tid = threadIdx.x;
    float cnt = cntR[j];                          // raw count
    __syncthreads();
    float cema = 0.99f * cc_in[j] + 0.01f * cnt;
    bool usage = (cema >= 1.0f);
    float denom = fmaxf(cema, 1e-10f);
    const int jimg = j >> 10, jt = j & 1023;
    for (int c = tid; c < CDIM; c += 256) {
        float ns = sumR[(size_t)j * CDIM + c];
        float sema = 0.99f * cs_in[(size_t)j * CDIM + c] + 0.01f * ns;
        sumR[(size_t)j * CDIM + c] = sema;        // code_sum_ema out
        float upd = sema / denom;
        float rnd = x[((size_t)jimg * CDIM + c) * TLEN + jt];
        ncb[(size_t)j * CDIM + c] = usage ? upd : rnd;
    }
    if (tid == 0) cntR[j] = cema;                 // code_count_ema out
}

// ---------------------------------------------------------------------------
extern "C" void kernel_launch(void* const* d_in, const int* in_sizes, int n_in,
                              void* d_out, int out_size) {
    const float* x  = (const float*)d_in[0];
    const float* cb = (const float*)d_in[1];
    const float* cs = (const float*)d_in[2];
    const float* cc = (const float*)d_in[3];
    float* out  = (float*)d_out;
    float* ncb  = out + OFF_NCB;
    float* sumR = out + OFF_SUM;
    float* cntR = out + OFF_CNT;

    k_init<<<(NB * CDIM) / 256, 256>>>(sumR, cntR);
    k_cnorm<<<NB / 8, 256>>>(cb);
    dim3 g(NB / 128, NROWS / 128);                // (16, 256)
    k_argmin<<<g, 256>>>(x, cb);
    dim3 gs(NROWS / 32, CDIM / 128);              // (1024, 4)
    k_scatter<<<gs, 256>>>(x, cb, out, sumR, cntR);
    k_perp<<<1, 256>>>(out, cntR);
    k_final<<<NB, 256>>>(x, cs, cc, sumR, cntR, ncb);
}

// round 6
// speedup vs baseline: 3.4595x; 2.2527x over previous
#include <cuda_runtime.h>
#include <cuda_bf16.h>
#include <cuda_fp16.h>
#include <cstdint>

#define NIMG 32
#define CDIM 512
#define TLEN 1024
#define NROWS (NIMG * TLEN)   // 32768
#define NB    2048

#define OFF_LOSS  16777216
#define OFF_PERP  16777217
#define OFF_NCB   16777218
#define OFF_SUM   (OFF_NCB + NB * CDIM)
#define OFF_CNT   (OFF_SUM + NB * CDIM)

#define MARGIN 16.0f

__device__ float          g_xf[NROWS * CDIM];   // x_flat fp32 [row][c]
__device__ __nv_bfloat16  g_xb[NROWS * CDIM];   // x_flat bf16
__device__ __nv_bfloat16  g_cbb[NB * CDIM];     // codebook bf16
__device__ __half         g_dist[(size_t)NROWS * NB];  // approx distances
__device__ int    g_idx[NROWS];
__device__ float  g_cnorm[NB];
__device__ double g_loss;

__device__ __forceinline__ unsigned long long packKey(float s, unsigned j) {
    unsigned u = __float_as_uint(s);
    u = (u & 0x80000000u) ? ~u : (u | 0x80000000u);   // order-preserving map
    return ((unsigned long long)u << 32) | j;
}
__device__ __forceinline__ uint32_t smem_u32(const void* p) {
    uint32_t a;
    asm("{ .reg .u64 t; cvta.to.shared.u64 t, %1; cvt.u32.u64 %0, t; }" : "=r"(a) : "l"(p));
    return a;
}
#define CP_ASYNC16(sm, gp) \
    asm volatile("cp.async.cg.shared.global [%0], [%1], 16;" :: "r"(sm), "l"(gp))
#define CP_COMMIT() asm volatile("cp.async.commit_group;")
#define CP_WAIT1()  asm volatile("cp.async.wait_group 1;")
#define CP_WAIT0()  asm volatile("cp.async.wait_group 0;")

#define MMA16816(d, a, b)                                                     \
    asm volatile("mma.sync.aligned.m16n8k16.row.col.f32.bf16.bf16.f32 "       \
                 "{%0,%1,%2,%3}, {%4,%5,%6,%7}, {%8,%9}, {%0,%1,%2,%3};"      \
                 : "+f"((d)[0]), "+f"((d)[1]), "+f"((d)[2]), "+f"((d)[3])     \
                 : "r"((a)[0]), "r"((a)[1]), "r"((a)[2]), "r"((a)[3]),        \
                   "r"((b)[0]), "r"((b)[1]))

// ---------------------------------------------------------------------------
// 1) init accumulators (sumR/cntR live in d_out)
// ---------------------------------------------------------------------------
__global__ void k_init(float* __restrict__ sumR, float* __restrict__ cntR) {
    int i = blockIdx.x * 256 + threadIdx.x;           // covers NB*CDIM
    sumR[i] = 0.0f;
    if (i < NB) cntR[i] = 0.0f;
    if (i == 0) g_loss = 0.0;
}

// ---------------------------------------------------------------------------
// 2) codebook row norms (exact fp32) + bf16 codebook copy
// ---------------------------------------------------------------------------
__global__ void k_cnorm(const float* __restrict__ cb) {
    int warp = blockIdx.x * 8 + (threadIdx.x >> 5);
    int lane = threadIdx.x & 31;
    const float* row = cb + (size_t)warp * CDIM;
    float s = 0.0f;
#pragma unroll
    for (int i = 0; i < CDIM / 32; i++) { float v = row[lane + i * 32]; s += v * v; }
#pragma unroll
    for (int o = 16; o > 0; o >>= 1) s += __shfl_xor_sync(0xFFFFFFFFu, s, o);
    if (lane == 0) g_cnorm[warp] = s;
}
__global__ void k_cbprep(const float* __restrict__ cb) {
    int i = blockIdx.x * 256 + threadIdx.x;           // covers NB*CDIM
    g_cbb[i] = __float2bfloat16(cb[i]);
}

// ---------------------------------------------------------------------------
// 3) transpose x [img][c][t] -> x_flat [row][c], fp32 + bf16 copies
// ---------------------------------------------------------------------------
__global__ void k_split(const float* __restrict__ x) {
    __shared__ float tile[32][33];
    const int tid = threadIdx.x;
    const int tx = tid & 31, ty = tid >> 5;           // 32 x 8
    const int t0 = blockIdx.x * 32, c0 = blockIdx.y * 32, img = blockIdx.z;
#pragma unroll
    for (int i = 0; i < 4; i++) {
        int c = c0 + ty + i * 8;
        tile[ty + i * 8][tx] = x[((size_t)img * CDIM + c) * TLEN + t0 + tx];
    }
    __syncthreads();
#pragma unroll
    for (int i = 0; i < 4; i++) {
        int t = t0 + ty + i * 8, c = c0 + tx;
        float v = tile[tx][ty + i * 8];
        size_t o = ((size_t)img * TLEN + t) * CDIM + c;
        g_xf[o] = v;
        g_xb[o] = __float2bfloat16(v);
    }
}

// ---------------------------------------------------------------------------
// 4) bf16 HMMA GEMM: approx dist = ||c||^2 - 2 x.c  -> g_dist (fp16)
//    CTA 256thr: tile M128 x N128, K=512 in 32-chunks, cp.async dbl-buffer.
//    Warp (wm=warp&3, wn=warp>>2): 32 rows x 64 cols = 2x8 m16n8k16 tiles.
// ---------------------------------------------------------------------------
__global__ __launch_bounds__(256, 2)
void k_dist() {
    __shared__ __align__(16) __nv_bfloat16 As[2][128][40];
    __shared__ __align__(16) __nv_bfloat16 Bs[2][128][40];
    __shared__ float cnS[128];

    const int tid = threadIdx.x;
    const int warp = tid >> 5, lane = tid & 31;
    const int wm = warp & 3, wn = warp >> 2;
    const int m0 = blockIdx.y * 128, j0 = blockIdx.x * 128;

    if (tid < 128) cnS[tid] = g_cnorm[j0 + tid];

    const int lr = tid >> 2, lq = tid & 3;            // loader mapping (u = tid, tid+256)
    auto issue = [&](int buf, int kt) {
#pragma unroll
        for (int s = 0; s < 2; s++) {
            int r = lr + s * 64;
            uint32_t sa = smem_u32(&As[buf][r][lq * 8]);
            uint32_t sb = smem_u32(&Bs[buf][r][lq * 8]);
            CP_ASYNC16(sa, &g_xb[(size_t)(m0 + r) * CDIM + kt + lq * 8]);
            CP_ASYNC16(sb, &g_cbb[(size_t)(j0 + r) * CDIM + kt + lq * 8]);
        }
        CP_COMMIT();
    };

    float acc[2][8][4];
#pragma unroll
    for (int mt = 0; mt < 2; mt++)
#pragma unroll
        for (int nt = 0; nt < 8; nt++)
#pragma unroll
            for (int e = 0; e < 4; e++) acc[mt][nt][e] = 0.0f;

    issue(0, 0);
    for (int ch = 0; ch < 16; ch++) {
        int buf = ch & 1;
        if (ch < 15) { issue(buf ^ 1, (ch + 1) * 32); CP_WAIT1(); }
        else         { CP_WAIT0(); }
        __syncthreads();

        const __nv_bfloat16 (*A)[40] = As[buf];
        const __nv_bfloat16 (*B)[40] = Bs[buf];
#pragma unroll
        for (int ks = 0; ks < 2; ks++) {
            const int c0 = ks * 16 + (lane & 3) * 2;
            const int rA = lane >> 2;
            uint32_t a[2][4], b[8][2];
#pragma unroll
            for (int mt = 0; mt < 2; mt++) {
                int rb = wm * 32 + mt * 16 + rA;
                a[mt][0] = *(const uint32_t*)&A[rb][c0];
                a[mt][1] = *(const uint32_t*)&A[rb + 8][c0];
                a[mt][2] = *(const uint32_t*)&A[rb][c0 + 8];
                a[mt][3] = *(const uint32_t*)&A[rb + 8][c0 + 8];
            }
#pragma unroll
            for (int nt = 0; nt < 8; nt++) {
                int n = wn * 64 + nt * 8 + rA;
                b[nt][0] = *(const uint32_t*)&B[n][c0];
                b[nt][1] = *(const uint32_t*)&B[n][c0 + 8];
            }
#pragma unroll
            for (int mt = 0; mt < 2; mt++)
#pragma unroll
                for (int nt = 0; nt < 8; nt++)
                    MMA16816(acc[mt][nt], a[mt], b[nt]);
        }
        __syncthreads();
    }

    // epilogue: dapx = cnorm - 2*dot -> fp16
#pragma unroll
    for (int mt = 0; mt < 2; mt++)
#pragma unroll
        for (int nt = 0; nt < 8; nt++) {
            int rr = m0 + wm * 32 + mt * 16 + (lane >> 2);
            int cc = wn * 64 + nt * 8 + (lane & 3) * 2;
            float s0 = cnS[cc]     - 2.0f * acc[mt][nt][0];
            float s1 = cnS[cc + 1] - 2.0f * acc[mt][nt][1];
            float s2 = cnS[cc]     - 2.0f * acc[mt][nt][2];
            float s3 = cnS[cc + 1] - 2.0f * acc[mt][nt][3];
            *(__half2*)&g_dist[(size_t)rr * NB + j0 + cc]       = __floats2half2_rn(s0, s1);
            *(__half2*)&g_dist[(size_t)(rr + 8) * NB + j0 + cc] = __floats2half2_rn(s2, s3);
        }
}

// ---------------------------------------------------------------------------
// 5) candidate scan + exact fp32 rescore. One warp per row.
// ---------------------------------------------------------------------------
__global__ __launch_bounds__(256)
void k_cand(const float* __restrict__ cb) {
    const int warp = threadIdx.x >> 5, lane = threadIdx.x & 31;
    const int row = blockIdx.x * 8 + warp;

    const uint4* dp = (const uint4*)(g_dist + (size_t)row * NB);
    uint4 v[8];
#pragma unroll
    for (int i = 0; i < 8; i++) v[i] = dp[lane + i * 32];

    float mn = 1e30f;
#pragma unroll
    for (int i = 0; i < 8; i++) {
        const uint32_t* w = (const uint32_t*)&v[i];
#pragma unroll
        for (int q = 0; q < 4; q++) {
            float2 f = __half22float2(*(const __half2*)&w[q]);
            mn = fminf(mn, fminf(f.x, f.y));
        }
    }
#pragma unroll
    for (int o = 16; o > 0; o >>= 1) mn = fminf(mn, __shfl_xor_sync(0xFFFFFFFFu, mn, o));
    const float thr = mn + MARGIN;

    const float* xr = g_xf + (size_t)row * CDIM;
    unsigned long long best = 0xFFFFFFFFFFFFFFFFull;
#pragma unroll
    for (int i = 0; i < 8; i++) {
        const uint32_t* w = (const uint32_t*)&v[i];
#pragma unroll
        for (int q = 0; q < 4; q++) {
            float2 f = __half22float2(*(const __half2*)&w[q]);
            int jb = (lane + i * 32) * 8 + q * 2;
            unsigned m = __ballot_sync(0xFFFFFFFFu, f.x <= thr || f.y <= thr);
            while (m) {
                int src = __ffs(m) - 1; m &= m - 1;
                int jj  = __shfl_sync(0xFFFFFFFFu, jb, src);
                float fx = __shfl_sync(0xFFFFFFFFu, f.x, src);
                float fy = __shfl_sync(0xFFFFFFFFu, f.y, src);
#pragma unroll
                for (int h = 0; h < 2; h++) {
                    float fv = h ? fy : fx;
                    if (fv > thr) continue;
                    int j = jj + h;
                    const float* cr = cb + (size_t)j * CDIM;
                    float d = 0.0f;
#pragma unroll
                    for (int qq = 0; qq < 16; qq++)
                        d += xr[lane + qq * 32] * cr[lane + qq * 32];
#pragma unroll
                    for (int o = 16; o > 0; o >>= 1) d += __shfl_xor_sync(0xFFFFFFFFu, d, o);
                    float s = g_cnorm[j] - 2.0f * d;
                    unsigned long long k = packKey(s, (unsigned)j);
                    if (k < best) best = k;
                }
            }
        }
    }
    if (lane == 0) g_idx[row] = (int)(best & 0xFFFFFFFFu);
}

// ---------------------------------------------------------------------------
// 6) gather codebook -> x_d_out, segment sums + counts, commit loss.
// ---------------------------------------------------------------------------
__global__ void k_scatter(const float* __restrict__ x, const float* __restrict__ cb,
                          float* __restrict__ out, float* __restrict__ sumR,
                          float* __restrict__ cntR) {
    __shared__ int sidx[32];
    __shared__ float lred[256];
    const int tid = threadIdx.x;
    const int r0 = blockIdx.x * 32;
    const int cbase = blockIdx.y * 128;
    const int img = r0 >> 10, t0 = r0 & 1023;

    if (tid < 32) {
        int idx = g_idx[r0 + tid];
        sidx[tid] = idx;
        if (blockIdx.y == 0) atomicAdd(&cntR[idx], 1.0f);
    }
    __syncthreads();

    const int tt = tid & 31;
    const int c0 = cbase + (tid >> 5);
    const int idx = sidx[tt];
    const float* cbrow = cb + (size_t)idx * CDIM;
    float loss = 0.0f;
#pragma unroll
    for (int ci = 0; ci < 16; ci++) {
        int c = c0 + ci * 8;
        float cv = cbrow[c];
        size_t xoff = ((size_t)img * CDIM + c) * TLEN + t0 + tt;
        float xv = x[xoff];
        out[xoff] = cv;
        atomicAdd(&sumR[(size_t)idx * CDIM + c], xv);
        float d = xv - cv;
        loss += d * d;
    }
    lred[tid] = loss;
    __syncthreads();
    for (int o = 128; o > 0; o >>= 1) {
        if (tid < o) lred[tid] += lred[tid + o];
        __syncthreads();
    }
    if (tid == 0) atomicAdd(&g_loss, (double)lred[0]);
}

// ---------------------------------------------------------------------------
// 7) perplexity (raw counts; total exactly 32768) + commit loss
// ---------------------------------------------------------------------------
__global__ void k_perp(float* __restrict__ out, const float* __restrict__ cntR) {
    __shared__ double sred[256];
    const int tid = threadIdx.x;
    double s = 0.0;
    for (int j = tid; j < NB; j += 256) {
        float cnt = cntR[j];
        float prob = cnt / (32768.0f + 1e-10f);
        s += (double)(prob * logf(prob + 1e-7f));
    }
    sred[tid] = s;
    __syncthreads();
    for (int o = 128; o > 0; o >>= 1) {
        if (tid < o) sred[tid] += sred[tid + o];
        __syncthreads();
    }
    if (tid == 0) {
        out[OFF_PERP] = (float)exp(-sred[0]);
        out[OFF_LOSS] = (float)(g_loss / (double)((size_t)NROWS * CDIM));
    }
}

// ---------------------------------------------------------------------------
// 8) EMA updates + codebook reset
// ---------------------------------------------------------------------------
__global__ void k_final(const float* __restrict__ x, const float* __restrict__ cs_in,
                        const float* __restrict__ cc_in, float* __restrict__ sumR,
                        float* __restrict__ cntR, float* __restrict__ ncb) {
    const int j = blockIdx.x;
    const int tid = threadIdx.x;
    float cnt = cntR[j];
    __syncthreads();
    float cema = 0.99f * cc_in[j] + 0.01f * cnt;
    bool usage = (cema >= 1.0f);
    float denom = fmaxf(cema, 1e-10f);
    const int jimg = j >> 10, jt = j & 1023;
    for (int c = tid; c < CDIM; c += 256) {
        float ns = sumR[(size_t)j * CDIM + c];
        float sema = 0.99f * cs_in[(size_t)j * CDIM + c] + 0.01f * ns;
        sumR[(size_t)j * CDIM + c] = sema;
        float upd = sema / denom;
        float rnd = x[((size_t)jimg * CDIM + c) * TLEN + jt];
        ncb[(size_t)j * CDIM + c] = usage ? upd : rnd;
    }
    if (tid == 0) cntR[j] = cema;
}

// ---------------------------------------------------------------------------
extern "C" void kernel_launch(void* const* d_in, const int* in_sizes, int n_in,
                              void* d_out, int out_size) {
    const float* x  = (const float*)d_in[0];
    const float* cb = (const float*)d_in[1];
    const float* cs = (const float*)d_in[2];
    const float* cc = (const float*)d_in[3];
    float* out  = (float*)d_out;
    float* ncb  = out + OFF_NCB;
    float* sumR = out + OFF_SUM;
    float* cntR = out + OFF_CNT;

    k_init<<<(NB * CDIM) / 256, 256>>>(sumR, cntR);
    k_cnorm<<<NB / 8, 256>>>(cb);
    k_cbprep<<<(NB * CDIM) / 256, 256>>>(cb);
    k_split<<<dim3(TLEN / 32, CDIM / 32, NIMG), 256>>>(x);
    k_dist<<<dim3(NB / 128, NROWS / 128), 256>>>();
    k_cand<<<NROWS / 8, 256>>>(cb);
    dim3 gs(NROWS / 32, CDIM / 128);
    k_scatter<<<gs, 256>>>(x, cb, out, sumR, cntR);
    k_perp<<<1, 256>>>(out, cntR);
    k_final<<<NB, 256>>>(x, cs, cc, sumR, cntR, ncb);
}

// round 7
// speedup vs baseline: 3.9416x; 1.1394x over previous
#include <cuda_runtime.h>
#include <cuda_bf16.h>
#include <cuda_fp16.h>
#include <cstdint>

#define NIMG 32
#define CDIM 512
#define TLEN 1024
#define NROWS (NIMG * TLEN)   // 32768
#define NB    2048

#define OFF_LOSS  16777216
#define OFF_PERP  16777217
#define OFF_NCB   16777218
#define OFF_SUM   (OFF_NCB + NB * CDIM)
#define OFF_CNT   (OFF_SUM + NB * CDIM)

#define MARGIN 16.0f

__device__ float          g_xf[NROWS * CDIM];   // x_flat fp32 [row][c]
__device__ __nv_bfloat16  g_xb[NROWS * CDIM];   // x_flat bf16
__device__ __nv_bfloat16  g_cbb[NB * CDIM];     // codebook bf16
__device__ __half         g_dist[(size_t)NROWS * NB];  // approx distances
__device__ int    g_idx[NROWS];
__device__ int    g_cnt[NB];                    // raw counts (int)
__device__ int    g_bstart[NB + 1];             // bucket offsets
__device__ int    g_bcur[NB];                   // fill cursors
__device__ int    g_blist[NROWS];               // rows grouped by code
__device__ float  g_cnorm[NB];
__device__ double g_loss;

__device__ __forceinline__ unsigned long long packKey(float s, unsigned j) {
    unsigned u = __float_as_uint(s);
    u = (u & 0x80000000u) ? ~u : (u | 0x80000000u);   // order-preserving map
    return ((unsigned long long)u << 32) | j;
}
__device__ __forceinline__ uint32_t smem_u32(const void* p) {
    uint32_t a;
    asm("{ .reg .u64 t; cvta.to.shared.u64 t, %1; cvt.u32.u64 %0, t; }" : "=r"(a) : "l"(p));
    return a;
}
#define CP_ASYNC16(sm, gp) \
    asm volatile("cp.async.cg.shared.global [%0], [%1], 16;" :: "r"(sm), "l"(gp))
#define CP_COMMIT() asm volatile("cp.async.commit_group;")
#define CP_WAIT1()  asm volatile("cp.async.wait_group 1;")
#define CP_WAIT0()  asm volatile("cp.async.wait_group 0;")

#define MMA16816(d, a, b)                                                     \
    asm volatile("mma.sync.aligned.m16n8k16.row.col.f32.bf16.bf16.f32 "       \
                 "{%0,%1,%2,%3}, {%4,%5,%6,%7}, {%8,%9}, {%0,%1,%2,%3};"      \
                 : "+f"((d)[0]), "+f"((d)[1]), "+f"((d)[2]), "+f"((d)[3])     \
                 : "r"((a)[0]), "r"((a)[1]), "r"((a)[2]), "r"((a)[3]),        \
                   "r"((b)[0]), "r"((b)[1]))

// ---------------------------------------------------------------------------
// 1) init
// ---------------------------------------------------------------------------
__global__ void k_init() {
    int i = blockIdx.x * 256 + threadIdx.x;           // covers NB
    g_cnt[i] = 0;
    if (i == 0) g_loss = 0.0;
}

// ---------------------------------------------------------------------------
// 2) codebook row norms (exact fp32) + bf16 codebook copy
// ---------------------------------------------------------------------------
__global__ void k_cnorm(const float* __restrict__ cb) {
    int warp = blockIdx.x * 8 + (threadIdx.x >> 5);
    int lane = threadIdx.x & 31;
    const float* row = cb + (size_t)warp * CDIM;
    float s = 0.0f;
#pragma unroll
    for (int i = 0; i < CDIM / 32; i++) { float v = row[lane + i * 32]; s += v * v; }
#pragma unroll
    for (int o = 16; o > 0; o >>= 1) s += __shfl_xor_sync(0xFFFFFFFFu, s, o);
    if (lane == 0) g_cnorm[warp] = s;
}
__global__ void k_cbprep(const float* __restrict__ cb) {
    int i = blockIdx.x * 256 + threadIdx.x;           // covers NB*CDIM
    g_cbb[i] = __float2bfloat16(cb[i]);
}

// ---------------------------------------------------------------------------
// 3) transpose x [img][c][t] -> x_flat [row][c], fp32 + bf16 copies
// ---------------------------------------------------------------------------
__global__ void k_split(const float* __restrict__ x) {
    __shared__ float tile[32][33];
    const int tid = threadIdx.x;
    const int tx = tid & 31, ty = tid >> 5;           // 32 x 8
    const int t0 = blockIdx.x * 32, c0 = blockIdx.y * 32, img = blockIdx.z;
#pragma unroll
    for (int i = 0; i < 4; i++) {
        int c = c0 + ty + i * 8;
        tile[ty + i * 8][tx] = x[((size_t)img * CDIM + c) * TLEN + t0 + tx];
    }
    __syncthreads();
#pragma unroll
    for (int i = 0; i < 4; i++) {
        int t = t0 + ty + i * 8, c = c0 + tx;
        float v = tile[tx][ty + i * 8];
        size_t o = ((size_t)img * TLEN + t) * CDIM + c;
        g_xf[o] = v;
        g_xb[o] = __float2bfloat16(v);
    }
}

// ---------------------------------------------------------------------------
// 4) bf16 HMMA GEMM: approx dist = ||c||^2 - 2 x.c  -> g_dist (fp16)
// ---------------------------------------------------------------------------
__global__ __launch_bounds__(256, 2)
void k_dist() {
    __shared__ __align__(16) __nv_bfloat16 As[2][128][40];
    __shared__ __align__(16) __nv_bfloat16 Bs[2][128][40];
    __shared__ float cnS[128];

    const int tid = threadIdx.x;
    const int warp = tid >> 5, lane = tid & 31;
    const int wm = warp & 3, wn = warp >> 2;
    const int m0 = blockIdx.y * 128, j0 = blockIdx.x * 128;

    if (tid < 128) cnS[tid] = g_cnorm[j0 + tid];

    const int lr = tid >> 2, lq = tid & 3;
    auto issue = [&](int buf, int kt) {
#pragma unroll
        for (int s = 0; s < 2; s++) {
            int r = lr + s * 64;
            uint32_t sa = smem_u32(&As[buf][r][lq * 8]);
            uint32_t sb = smem_u32(&Bs[buf][r][lq * 8]);
            CP_ASYNC16(sa, &g_xb[(size_t)(m0 + r) * CDIM + kt + lq * 8]);
            CP_ASYNC16(sb, &g_cbb[(size_t)(j0 + r) * CDIM + kt + lq * 8]);
        }
        CP_COMMIT();
    };

    float acc[2][8][4];
#pragma unroll
    for (int mt = 0; mt < 2; mt++)
#pragma unroll
        for (int nt = 0; nt < 8; nt++)
#pragma unroll
            for (int e = 0; e < 4; e++) acc[mt][nt][e] = 0.0f;

    issue(0, 0);
    for (int ch = 0; ch < 16; ch++) {
        int buf = ch & 1;
        if (ch < 15) { issue(buf ^ 1, (ch + 1) * 32); CP_WAIT1(); }
        else         { CP_WAIT0(); }
        __syncthreads();

        const __nv_bfloat16 (*A)[40] = As[buf];
        const __nv_bfloat16 (*B)[40] = Bs[buf];
#pragma unroll
        for (int ks = 0; ks < 2; ks++) {
            const int c0 = ks * 16 + (lane & 3) * 2;
            const int rA = lane >> 2;
            uint32_t a[2][4], b[8][2];
#pragma unroll
            for (int mt = 0; mt < 2; mt++) {
                int rb = wm * 32 + mt * 16 + rA;
                a[mt][0] = *(const uint32_t*)&A[rb][c0];
                a[mt][1] = *(const uint32_t*)&A[rb + 8][c0];
                a[mt][2] = *(const uint32_t*)&A[rb][c0 + 8];
                a[mt][3] = *(const uint32_t*)&A[rb + 8][c0 + 8];
            }
#pragma unroll
            for (int nt = 0; nt < 8; nt++) {
                int n = wn * 64 + nt * 8 + rA;
                b[nt][0] = *(const uint32_t*)&B[n][c0];
                b[nt][1] = *(const uint32_t*)&B[n][c0 + 8];
            }
#pragma unroll
            for (int mt = 0; mt < 2; mt++)
#pragma unroll
                for (int nt = 0; nt < 8; nt++)
                    MMA16816(acc[mt][nt], a[mt], b[nt]);
        }
        __syncthreads();
    }

#pragma unroll
    for (int mt = 0; mt < 2; mt++)
#pragma unroll
        for (int nt = 0; nt < 8; nt++) {
            int rr = m0 + wm * 32 + mt * 16 + (lane >> 2);
            int cc = wn * 64 + nt * 8 + (lane & 3) * 2;
            float s0 = cnS[cc]     - 2.0f * acc[mt][nt][0];
            float s1 = cnS[cc + 1] - 2.0f * acc[mt][nt][1];
            float s2 = cnS[cc]     - 2.0f * acc[mt][nt][2];
            float s3 = cnS[cc + 1] - 2.0f * acc[mt][nt][3];
            *(__half2*)&g_dist[(size_t)rr * NB + j0 + cc]       = __floats2half2_rn(s0, s1);
            *(__half2*)&g_dist[(size_t)(rr + 8) * NB + j0 + cc] = __floats2half2_rn(s2, s3);
        }
}

// ---------------------------------------------------------------------------
// 5) candidate scan + exact fp32 rescore + count. One warp per row.
// ---------------------------------------------------------------------------
__global__ __launch_bounds__(256)
void k_cand(const float* __restrict__ cb) {
    const int warp = threadIdx.x >> 5, lane = threadIdx.x & 31;
    const int row = blockIdx.x * 8 + warp;

    const uint4* dp = (const uint4*)(g_dist + (size_t)row * NB);
    uint4 v[8];
#pragma unroll
    for (int i = 0; i < 8; i++) v[i] = dp[lane + i * 32];

    float mn = 1e30f;
#pragma unroll
    for (int i = 0; i < 8; i++) {
        const uint32_t* w = (const uint32_t*)&v[i];
#pragma unroll
        for (int q = 0; q < 4; q++) {
            float2 f = __half22float2(*(const __half2*)&w[q]);
            mn = fminf(mn, fminf(f.x, f.y));
        }
    }
#pragma unroll
    for (int o = 16; o > 0; o >>= 1) mn = fminf(mn, __shfl_xor_sync(0xFFFFFFFFu, mn, o));
    const float thr = mn + MARGIN;

    const float* xr = g_xf + (size_t)row * CDIM;
    unsigned long long best = 0xFFFFFFFFFFFFFFFFull;
#pragma unroll
    for (int i = 0; i < 8; i++) {
        const uint32_t* w = (const uint32_t*)&v[i];
#pragma unroll
        for (int q = 0; q < 4; q++) {
            float2 f = __half22float2(*(const __half2*)&w[q]);
            int jb = (lane + i * 32) * 8 + q * 2;
            unsigned m = __ballot_sync(0xFFFFFFFFu, f.x <= thr || f.y <= thr);
            while (m) {
                int src = __ffs(m) - 1; m &= m - 1;
                int jj  = __shfl_sync(0xFFFFFFFFu, jb, src);
                float fx = __shfl_sync(0xFFFFFFFFu, f.x, src);
                float fy = __shfl_sync(0xFFFFFFFFu, f.y, src);
#pragma unroll
                for (int h = 0; h < 2; h++) {
                    float fv = h ? fy : fx;
                    if (fv > thr) continue;
                    int j = jj + h;
                    const float* cr = cb + (size_t)j * CDIM;
                    float d = 0.0f;
#pragma unroll
                    for (int qq = 0; qq < 16; qq++)
                        d += xr[lane + qq * 32] * cr[lane + qq * 32];
#pragma unroll
                    for (int o = 16; o > 0; o >>= 1) d += __shfl_xor_sync(0xFFFFFFFFu, d, o);
                    float s = g_cnorm[j] - 2.0f * d;
                    unsigned long long k = packKey(s, (unsigned)j);
                    if (k < best) best = k;
                }
            }
        }
    }
    if (lane == 0) {
        int idx = (int)(best & 0xFFFFFFFFu);
        g_idx[row] = idx;
        atomicAdd(&g_cnt[idx], 1);
    }
}

// ---------------------------------------------------------------------------
// 6) exclusive prefix scan over 2048 counts -> bucket offsets + cursors
// ---------------------------------------------------------------------------
__global__ void k_prefix() {
    __shared__ int sh[1024];
    const int t = threadIdx.x;                        // 1024 threads
    int c0 = g_cnt[2 * t], c1 = g_cnt[2 * t + 1];
    int v = c0 + c1;
    sh[t] = v;
    __syncthreads();
#pragma unroll
    for (int o = 1; o < 1024; o <<= 1) {
        int add = (t >= o) ? sh[t - o] : 0;
        __syncthreads();
        sh[t] += add;
        __syncthreads();
    }
    int excl = (t == 0) ? 0 : sh[t - 1];              // exclusive over pairs
    g_bstart[2 * t]     = excl;
    g_bstart[2 * t + 1] = excl + c0;
    g_bcur[2 * t]       = excl;
    g_bcur[2 * t + 1]   = excl + c0;
    if (t == 1023) g_bstart[2048] = sh[1023];
}

// 7) fill bucket lists
__global__ void k_fill() {
    int row = blockIdx.x * 256 + threadIdx.x;         // covers NROWS
    int idx = g_idx[row];
    int pos = atomicAdd(&g_bcur[idx], 1);
    g_blist[pos] = row;
}

// ---------------------------------------------------------------------------
// 8) x_d_out write (transposed) + commit loss.  No segment atomics.
// ---------------------------------------------------------------------------
__global__ void k_out(const float* __restrict__ x, const float* __restrict__ cb,
                      float* __restrict__ out) {
    __shared__ int sidx[32];
    __shared__ float lred[256];
    const int tid = threadIdx.x;
    const int r0 = blockIdx.x * 32;
    const int cbase = blockIdx.y * 128;
    const int img = r0 >> 10, t0 = r0 & 1023;

    if (tid < 32) sidx[tid] = g_idx[r0 + tid];
    __syncthreads();

    const int tt = tid & 31;
    const int c0 = cbase + (tid >> 5);
    const int idx = sidx[tt];
    const float* cbrow = cb + (size_t)idx * CDIM;
    float loss = 0.0f;
#pragma unroll
    for (int ci = 0; ci < 16; ci++) {
        int c = c0 + ci * 8;
        float cv = cbrow[c];
        size_t xoff = ((size_t)img * CDIM + c) * TLEN + t0 + tt;
        float xv = x[xoff];
        out[xoff] = cv;
        float d = xv - cv;
        loss += d * d;
    }
    lred[tid] = loss;
    __syncthreads();
    for (int o = 128; o > 0; o >>= 1) {
        if (tid < o) lred[tid] += lred[tid + o];
        __syncthreads();
    }
    if (tid == 0) atomicAdd(&g_loss, (double)lred[0]);
}

// ---------------------------------------------------------------------------
// 9) per-code segment sum (bucket gather) + EMA + codebook reset, fused.
//    One block per code, 256 threads; thread owns cols (tid, tid+256).
// ---------------------------------------------------------------------------
__global__ __launch_bounds__(256)
void k_sum(const float* __restrict__ cs_in, const float* __restrict__ cc_in,
           float* __restrict__ sumR, float* __restrict__ cntR,
           float* __restrict__ ncb) {
    const int j = blockIdx.x;
    const int tid = threadIdx.x;
    const int s = g_bstart[j], e = g_bstart[j + 1];

    float a0 = 0.0f, a1 = 0.0f;
    for (int i = s; i < e; i++) {
        const float* xr = g_xf + (size_t)g_blist[i] * CDIM;
        a0 += xr[tid];
        a1 += xr[tid + 256];
    }
    float cnt = (float)(e - s);
    float cema = 0.99f * cc_in[j] + 0.01f * cnt;
    bool usage = (cema >= 1.0f);
    float denom = fmaxf(cema, 1e-10f);
    const float* xj = g_xf + (size_t)j * CDIM;        // x_flat[j] for reset path

    float sema0 = 0.99f * cs_in[(size_t)j * CDIM + tid]       + 0.01f * a0;
    float sema1 = 0.99f * cs_in[(size_t)j * CDIM + tid + 256] + 0.01f * a1;
    sumR[(size_t)j * CDIM + tid]       = sema0;
    sumR[(size_t)j * CDIM + tid + 256] = sema1;
    ncb[(size_t)j * CDIM + tid]       = usage ? (sema0 / denom) : xj[tid];
    ncb[(size_t)j * CDIM + tid + 256] = usage ? (sema1 / denom) : xj[tid + 256];
    if (tid == 0) cntR[j] = cema;
}

// ---------------------------------------------------------------------------
// 10) perplexity (raw int counts; total exactly 32768) + commit loss
// ---------------------------------------------------------------------------
__global__ void k_perp(float* __restrict__ out) {
    __shared__ double sred[256];
    const int tid = threadIdx.x;
    double s = 0.0;
    for (int j = tid; j < NB; j += 256) {
        float cnt = (float)g_cnt[j];
        float prob = cnt / (32768.0f + 1e-10f);
        s += (double)(prob * logf(prob + 1e-7f));
    }
    sred[tid] = s;
    __syncthreads();
    for (int o = 128; o > 0; o >>= 1) {
        if (tid < o) sred[tid] += sred[tid + o];
        __syncthreads();
    }
    if (tid == 0) {
        out[OFF_PERP] = (float)exp(-sred[0]);
        out[OFF_LOSS] = (float)(g_loss / (double)((size_t)NROWS * CDIM));
    }
}

// ---------------------------------------------------------------------------
extern "C" void kernel_launch(void* const* d_in, const int* in_sizes, int n_in,
                              void* d_out, int out_size) {
    const float* x  = (const float*)d_in[0];
    const float* cb = (const float*)d_in[1];
    const float* cs = (const float*)d_in[2];
    const float* cc = (const float*)d_in[3];
    float* out  = (float*)d_out;
    float* ncb  = out + OFF_NCB;
    float* sumR = out + OFF_SUM;
    float* cntR = out + OFF_CNT;

    k_init<<<NB / 256, 256>>>();
    k_cnorm<<<NB / 8, 256>>>(cb);
    k_cbprep<<<(NB * CDIM) / 256, 256>>>(cb);
    k_split<<<dim3(TLEN / 32, CDIM / 32, NIMG), 256>>>(x);
    k_dist<<<dim3(NB / 128, NROWS / 128), 256>>>();
    k_cand<<<NROWS / 8, 256>>>(cb);
    k_prefix<<<1, 1024>>>();
    k_fill<<<NROWS / 256, 256>>>();
    dim3 go(NROWS / 32, CDIM / 128);
    k_out<<<go, 256>>>(x, cb, out);
    k_sum<<<NB, 256>>>(cs, cc, sumR, cntR, ncb);
    k_perp<<<1, 256>>>(out);
}

// round 8
// speedup vs baseline: 4.0517x; 1.0279x over previous
#include <cuda_runtime.h>
#include <cuda_bf16.h>
#include <cuda_fp16.h>
#include <cstdint>

#define NIMG 32
#define CDIM 512
#define TLEN 1024
#define NROWS (NIMG * TLEN)   // 32768
#define NB    2048

#define OFF_LOSS  16777216
#define OFF_PERP  16777217
#define OFF_NCB   16777218
#define OFF_SUM   (OFF_NCB + NB * CDIM)
#define OFF_CNT   (OFF_SUM + NB * CDIM)

#define MARGIN 16.0f

__device__ float          g_xf[NROWS * CDIM];   // x_flat fp32 [row][c]
__device__ __nv_bfloat16  g_xb[NROWS * CDIM];   // x_flat bf16
__device__ __nv_bfloat16  g_cbb[NB * CDIM];     // codebook bf16
__device__ __half         g_dist[(size_t)NROWS * NB];  // approx distances
__device__ int    g_idx[NROWS];
__device__ int    g_cnt[NB];                    // raw counts (int)
__device__ int    g_bstart[NB + 1];             // bucket offsets
__device__ int    g_bcur[NB];                   // fill cursors
__device__ int    g_blist[NROWS];               // rows grouped by code
__device__ float  g_cnorm[NB];
__device__ double g_loss;

__device__ __forceinline__ unsigned long long packKey(float s, unsigned j) {
    unsigned u = __float_as_uint(s);
    u = (u & 0x80000000u) ? ~u : (u | 0x80000000u);   // order-preserving map
    return ((unsigned long long)u << 32) | j;
}
__device__ __forceinline__ float unpackS(unsigned long long key) {
    unsigned u = (unsigned)(key >> 32);
    u = (u & 0x80000000u) ? (u & 0x7FFFFFFFu) : ~u;   // inverse map
    return __uint_as_float(u);
}
__device__ __forceinline__ uint32_t smem_u32(const void* p) {
    uint32_t a;
    asm("{ .reg .u64 t; cvta.to.shared.u64 t, %1; cvt.u32.u64 %0, t; }" : "=r"(a) : "l"(p));
    return a;
}
#define CP_ASYNC16(sm, gp) \
    asm volatile("cp.async.cg.shared.global [%0], [%1], 16;" :: "r"(sm), "l"(gp))
#define CP_COMMIT() asm volatile("cp.async.commit_group;")
#define CP_WAIT1()  asm volatile("cp.async.wait_group 1;")
#define CP_WAIT0()  asm volatile("cp.async.wait_group 0;")

#define MMA16816(d, a, b)                                                     \
    asm volatile("mma.sync.aligned.m16n8k16.row.col.f32.bf16.bf16.f32 "       \
                 "{%0,%1,%2,%3}, {%4,%5,%6,%7}, {%8,%9}, {%0,%1,%2,%3};"      \
                 : "+f"((d)[0]), "+f"((d)[1]), "+f"((d)[2]), "+f"((d)[3])     \
                 : "r"((a)[0]), "r"((a)[1]), "r"((a)[2]), "r"((a)[3]),        \
                   "r"((b)[0]), "r"((b)[1]))

// ---------------------------------------------------------------------------
// 1) init
// ---------------------------------------------------------------------------
__global__ void k_init() {
    int i = blockIdx.x * 256 + threadIdx.x;           // covers NB
    g_cnt[i] = 0;
    if (i == 0) g_loss = 0.0;
}

// ---------------------------------------------------------------------------
// 2) fused: codebook row norms (exact fp32) + bf16 codebook copy
// ---------------------------------------------------------------------------
__global__ void k_cbprep(const float* __restrict__ cb) {
    int warp = blockIdx.x * 8 + (threadIdx.x >> 5);
    int lane = threadIdx.x & 31;
    const float* row = cb + (size_t)warp * CDIM;
    __nv_bfloat16* brow = g_cbb + (size_t)warp * CDIM;
    float s = 0.0f;
#pragma unroll
    for (int i = 0; i < CDIM / 32; i++) {
        float v = row[lane + i * 32];
        s += v * v;
        brow[lane + i * 32] = __float2bfloat16(v);
    }
#pragma unroll
    for (int o = 16; o > 0; o >>= 1) s += __shfl_xor_sync(0xFFFFFFFFu, s, o);
    if (lane == 0) g_cnorm[warp] = s;
}

// ---------------------------------------------------------------------------
// 3) transpose x [img][c][t] -> x_flat [row][c], fp32 + bf16, float4 path
// ---------------------------------------------------------------------------
__global__ void k_split(const float* __restrict__ x) {
    __shared__ float tile[32][33];
    const int tid = threadIdx.x;
    const int tx = tid & 7, ty = tid >> 3;            // tx: t4-group, ty: c (load phase)
    const int t0 = blockIdx.x * 32, c0 = blockIdx.y * 32, img = blockIdx.z;

    float4 g = *(const float4*)&x[((size_t)img * CDIM + c0 + ty) * TLEN + t0 + tx * 4];
    tile[tx * 4 + 0][ty] = g.x;
    tile[tx * 4 + 1][ty] = g.y;
    tile[tx * 4 + 2][ty] = g.z;
    tile[tx * 4 + 3][ty] = g.w;
    __syncthreads();

    // store phase: ty is now t, tx is c4-group
    float4 v;
    v.x = tile[ty][tx * 4 + 0];
    v.y = tile[ty][tx * 4 + 1];
    v.z = tile[ty][tx * 4 + 2];
    v.w = tile[ty][tx * 4 + 3];
    size_t o = ((size_t)img * TLEN + t0 + ty) * CDIM + c0 + tx * 4;
    *(float4*)&g_xf[o] = v;
    __nv_bfloat162 b0 = {__float2bfloat16(v.x), __float2bfloat16(v.y)};
    __nv_bfloat162 b1 = {__float2bfloat16(v.z), __float2bfloat16(v.w)};
    *(__nv_bfloat162*)&g_xb[o]     = b0;
    *(__nv_bfloat162*)&g_xb[o + 2] = b1;
}

// ---------------------------------------------------------------------------
// 4) bf16 HMMA GEMM: approx dist = ||c||^2 - 2 x.c  -> g_dist (fp16)
// ---------------------------------------------------------------------------
__global__ __launch_bounds__(256, 2)
void k_dist() {
    __shared__ __align__(16) __nv_bfloat16 As[2][128][40];
    __shared__ __align__(16) __nv_bfloat16 Bs[2][128][40];
    __shared__ float cnS[128];

    const int tid = threadIdx.x;
    const int warp = tid >> 5, lane = tid & 31;
    const int wm = warp & 3, wn = warp >> 2;
    const int m0 = blockIdx.y * 128, j0 = blockIdx.x * 128;

    if (tid < 128) cnS[tid] = g_cnorm[j0 + tid];

    const int lr = tid >> 2, lq = tid & 3;
    auto issue = [&](int buf, int kt) {
#pragma unroll
        for (int s = 0; s < 2; s++) {
            int r = lr + s * 64;
            uint32_t sa = smem_u32(&As[buf][r][lq * 8]);
            uint32_t sb = smem_u32(&Bs[buf][r][lq * 8]);
            CP_ASYNC16(sa, &g_xb[(size_t)(m0 + r) * CDIM + kt + lq * 8]);
            CP_ASYNC16(sb, &g_cbb[(size_t)(j0 + r) * CDIM + kt + lq * 8]);
        }
        CP_COMMIT();
    };

    float acc[2][8][4];
#pragma unroll
    for (int mt = 0; mt < 2; mt++)
#pragma unroll
        for (int nt = 0; nt < 8; nt++)
#pragma unroll
            for (int e = 0; e < 4; e++) acc[mt][nt][e] = 0.0f;

    issue(0, 0);
    for (int ch = 0; ch < 16; ch++) {
        int buf = ch & 1;
        if (ch < 15) { issue(buf ^ 1, (ch + 1) * 32); CP_WAIT1(); }
        else         { CP_WAIT0(); }
        __syncthreads();

        const __nv_bfloat16 (*A)[40] = As[buf];
        const __nv_bfloat16 (*B)[40] = Bs[buf];
#pragma unroll
        for (int ks = 0; ks < 2; ks++) {
            const int c0 = ks * 16 + (lane & 3) * 2;
            const int rA = lane >> 2;
            uint32_t a[2][4], b[8][2];
#pragma unroll
            for (int mt = 0; mt < 2; mt++) {
                int rb = wm * 32 + mt * 16 + rA;
                a[mt][0] = *(const uint32_t*)&A[rb][c0];
                a[mt][1] = *(const uint32_t*)&A[rb + 8][c0];
                a[mt][2] = *(const uint32_t*)&A[rb][c0 + 8];
                a[mt][3] = *(const uint32_t*)&A[rb + 8][c0 + 8];
            }
#pragma unroll
            for (int nt = 0; nt < 8; nt++) {
                int n = wn * 64 + nt * 8 + rA;
                b[nt][0] = *(const uint32_t*)&B[n][c0];
                b[nt][1] = *(const uint32_t*)&B[n][c0 + 8];
            }
#pragma unroll
            for (int mt = 0; mt < 2; mt++)
#pragma unroll
                for (int nt = 0; nt < 8; nt++)
                    MMA16816(acc[mt][nt], a[mt], b[nt]);
        }
        __syncthreads();
    }

#pragma unroll
    for (int mt = 0; mt < 2; mt++)
#pragma unroll
        for (int nt = 0; nt < 8; nt++) {
            int rr = m0 + wm * 32 + mt * 16 + (lane >> 2);
            int cc = wn * 64 + nt * 8 + (lane & 3) * 2;
            float s0 = cnS[cc]     - 2.0f * acc[mt][nt][0];
            float s1 = cnS[cc + 1] - 2.0f * acc[mt][nt][1];
            float s2 = cnS[cc]     - 2.0f * acc[mt][nt][2];
            float s3 = cnS[cc + 1] - 2.0f * acc[mt][nt][3];
            *(__half2*)&g_dist[(size_t)rr * NB + j0 + cc]       = __floats2half2_rn(s0, s1);
            *(__half2*)&g_dist[(size_t)(rr + 8) * NB + j0 + cc] = __floats2half2_rn(s2, s3);
        }
}

// ---------------------------------------------------------------------------
// 5) candidate scan + exact fp32 rescore + count + commit-loss contribution.
//    One warp per row.  loss_row = ||x||^2 + s_best  (s_best exact fp32).
// ---------------------------------------------------------------------------
__global__ __launch_bounds__(256)
void k_cand(const float* __restrict__ cb) {
    __shared__ float lred[8];
    const int warp = threadIdx.x >> 5, lane = threadIdx.x & 31;
    const int row = blockIdx.x * 8 + warp;

    const uint4* dp = (const uint4*)(g_dist + (size_t)row * NB);
    uint4 v[8];
#pragma unroll
    for (int i = 0; i < 8; i++) v[i] = dp[lane + i * 32];

    float mn = 1e30f;
#pragma unroll
    for (int i = 0; i < 8; i++) {
        const uint32_t* w = (const uint32_t*)&v[i];
#pragma unroll
        for (int q = 0; q < 4; q++) {
            float2 f = __half22float2(*(const __half2*)&w[q]);
            mn = fminf(mn, fminf(f.x, f.y));
        }
    }
#pragma unroll
    for (int o = 16; o > 0; o >>= 1) mn = fminf(mn, __shfl_xor_sync(0xFFFFFFFFu, mn, o));
    const float thr = mn + MARGIN;

    const float* xr = g_xf + (size_t)row * CDIM;
    // ||x||^2 (warp-reduced fp32)
    float xn = 0.0f;
#pragma unroll
    for (int qq = 0; qq < 16; qq++) {
        float xv = xr[lane + qq * 32];
        xn += xv * xv;
    }
#pragma unroll
    for (int o = 16; o > 0; o >>= 1) xn += __shfl_xor_sync(0xFFFFFFFFu, xn, o);

    unsigned long long best = 0xFFFFFFFFFFFFFFFFull;
#pragma unroll
    for (int i = 0; i < 8; i++) {
        const uint32_t* w = (const uint32_t*)&v[i];
#pragma unroll
        for (int q = 0; q < 4; q++) {
            float2 f = __half22float2(*(const __half2*)&w[q]);
            int jb = (lane + i * 32) * 8 + q * 2;
            unsigned m = __ballot_sync(0xFFFFFFFFu, f.x <= thr || f.y <= thr);
            while (m) {
                int src = __ffs(m) - 1; m &= m - 1;
                int jj  = __shfl_sync(0xFFFFFFFFu, jb, src);
                float fx = __shfl_sync(0xFFFFFFFFu, f.x, src);
                float fy = __shfl_sync(0xFFFFFFFFu, f.y, src);
#pragma unroll
                for (int h = 0; h < 2; h++) {
                    float fv = h ? fy : fx;
                    if (fv > thr) continue;
                    int j = jj + h;
                    const float* cr = cb + (size_t)j * CDIM;
                    float d = 0.0f;
#pragma unroll
                    for (int qq = 0; qq < 16; qq++)
                        d += xr[lane + qq * 32] * cr[lane + qq * 32];
#pragma unroll
                    for (int o = 16; o > 0; o >>= 1) d += __shfl_xor_sync(0xFFFFFFFFu, d, o);
                    float s = g_cnorm[j] - 2.0f * d;
                    unsigned long long k = packKey(s, (unsigned)j);
                    if (k < best) best = k;
                }
            }
        }
    }
    if (lane == 0) {
        int idx = (int)(best & 0xFFFFFFFFu);
        g_idx[row] = idx;
        atomicAdd(&g_cnt[idx], 1);
        lred[warp] = xn + unpackS(best);              // row commit-loss
    }
    __syncthreads();
    if (threadIdx.x == 0) {
        float l = 0.0f;
#pragma unroll
        for (int i = 0; i < 8; i++) l += lred[i];
        atomicAdd(&g_loss, (double)l);
    }
}

// ---------------------------------------------------------------------------
// 6) prefix scan over counts -> bucket offsets/cursors; fused perplexity
// ---------------------------------------------------------------------------
__global__ void k_prefix(float* __restrict__ out) {
    __shared__ int sh[1024];
    __shared__ double pr[1024];
    const int t = threadIdx.x;                        // 1024 threads
    int c0 = g_cnt[2 * t], c1 = g_cnt[2 * t + 1];
    sh[t] = c0 + c1;
    {
        float p0 = (float)c0 / (32768.0f + 1e-10f);
        float p1 = (float)c1 / (32768.0f + 1e-10f);
        pr[t] = (double)(p0 * logf(p0 + 1e-7f)) + (double)(p1 * logf(p1 + 1e-7f));
    }
    __syncthreads();
#pragma unroll
    for (int o = 1; o < 1024; o <<= 1) {
        int add = (t >= o) ? sh[t - o] : 0;
        __syncthreads();
        sh[t] += add;
        __syncthreads();
    }
    int excl = (t == 0) ? 0 : sh[t - 1];
    g_bstart[2 * t]     = excl;
    g_bstart[2 * t + 1] = excl + c0;
    g_bcur[2 * t]       = excl;
    g_bcur[2 * t + 1]   = excl + c0;
    if (t == 1023) g_bstart[2048] = sh[1023];
    for (int o = 512; o > 0; o >>= 1) {
        if (t < o) pr[t] += pr[t + o];
        __syncthreads();
    }
    if (t == 0) out[OFF_PERP] = (float)exp(-pr[0]);
}

// 7) fill bucket lists
__global__ void k_fill() {
    int row = blockIdx.x * 256 + threadIdx.x;         // covers NROWS
    int idx = g_idx[row];
    int pos = atomicAdd(&g_bcur[idx], 1);
    g_blist[pos] = row;
}

// ---------------------------------------------------------------------------
// 8) x_d_out gather-write only (transposed layout)
// ---------------------------------------------------------------------------
__global__ void k_out(const float* __restrict__ cb, float* __restrict__ out) {
    __shared__ int sidx[32];
    const int tid = threadIdx.x;
    const int r0 = blockIdx.x * 32;
    const int cbase = blockIdx.y * 128;
    const int img = r0 >> 10, t0 = r0 & 1023;

    if (tid < 32) sidx[tid] = g_idx[r0 + tid];
    __syncthreads();

    const int tt = tid & 31;
    const int c0 = cbase + (tid >> 5);
    const int idx = sidx[tt];
    const float* cbrow = cb + (size_t)idx * CDIM;
#pragma unroll
    for (int ci = 0; ci < 16; ci++) {
        int c = c0 + ci * 8;
        out[((size_t)img * CDIM + c) * TLEN + t0 + tt] = cbrow[c];
    }
}

// ---------------------------------------------------------------------------
// 9) per-code segment sum (bucket gather) + EMA + reset; block 0 writes loss
// ---------------------------------------------------------------------------
__global__ __launch_bounds__(256)
void k_sum(const float* __restrict__ cs_in, const float* __restrict__ cc_in,
           float* __restrict__ sumR, float* __restrict__ cntR,
           float* __restrict__ ncb, float* __restrict__ out) {
    const int j = blockIdx.x;
    const int tid = threadIdx.x;
    const int s = g_bstart[j], e = g_bstart[j + 1];

    float a0 = 0.0f, a1 = 0.0f;
    for (int i = s; i < e; i++) {
        const float* xr = g_xf + (size_t)g_blist[i] * CDIM;
        a0 += xr[tid];
        a1 += xr[tid + 256];
    }
    float cnt = (float)(e - s);
    float cema = 0.99f * cc_in[j] + 0.01f * cnt;
    bool usage = (cema >= 1.0f);
    float denom = fmaxf(cema, 1e-10f);
    const float* xj = g_xf + (size_t)j * CDIM;        // x_flat[j] for reset path

    float sema0 = 0.99f * cs_in[(size_t)j * CDIM + tid]       + 0.01f * a0;
    float sema1 = 0.99f * cs_in[(size_t)j * CDIM + tid + 256] + 0.01f * a1;
    sumR[(size_t)j * CDIM + tid]       = sema0;
    sumR[(size_t)j * CDIM + tid + 256] = sema1;
    ncb[(size_t)j * CDIM + tid]       = usage ? (sema0 / denom) : xj[tid];
    ncb[(size_t)j * CDIM + tid + 256] = usage ? (sema1 / denom) : xj[tid + 256];
    if (tid == 0) {
        cntR[j] = cema;
        if (j == 0) out[OFF_LOSS] = (float)(g_loss / (double)((size_t)NROWS * CDIM));
    }
}

// ---------------------------------------------------------------------------
extern "C" void kernel_launch(void* const* d_in, const int* in_sizes, int n_in,
                              void* d_out, int out_size) {
    const float* x  = (const float*)d_in[0];
    const float* cb = (const float*)d_in[1];
    const float* cs = (const float*)d_in[2];
    const float* cc = (const float*)d_in[3];
    float* out  = (float*)d_out;
    float* ncb  = out + OFF_NCB;
    float* sumR = out + OFF_SUM;
    float* cntR = out + OFF_CNT;

    k_init<<<NB / 256, 256>>>();
    k_cbprep<<<NB / 8, 256>>>(cb);
    k_split<<<dim3(TLEN / 32, CDIM / 32, NIMG), 256>>>(x);
    k_dist<<<dim3(NB / 128, NROWS / 128), 256>>>();
    k_cand<<<NROWS / 8, 256>>>(cb);
    k_prefix<<<1, 1024>>>(out);
    k_fill<<<NROWS / 256, 256>>>();
    dim3 go(NROWS / 32, CDIM / 128);
    k_out<<<go, 256>>>(cb, out);
    k_sum<<<NB, 256>>>(cs, cc, sumR, cntR, ncb, out);
}

// round 9
// speedup vs baseline: 5.0016x; 1.2344x over previous
#include <cuda_runtime.h>
#include <cuda_bf16.h>
#include <cuda_fp16.h>
#include <cstdint>

#define NIMG 32
#define CDIM 512
#define TLEN 1024
#define NROWS (NIMG * TLEN)   // 32768
#define NB    2048

#define OFF_LOSS  16777216
#define OFF_PERP  16777217
#define OFF_NCB   16777218
#define OFF_SUM   (OFF_NCB + NB * CDIM)
#define OFF_CNT   (OFF_SUM + NB * CDIM)

#define MARGIN 16.0f
#define KSTAGE 4
#define STAGE_BYTES 20480          // (A:128x40 + B:128x40) bf16
#define DSMEM (KSTAGE * STAGE_BYTES)

__device__ float          g_xf[NROWS * CDIM];   // x_flat fp32 [row][c]
__device__ __nv_bfloat16  g_xb[NROWS * CDIM];   // x_flat bf16
__device__ __nv_bfloat16  g_cbb[NB * CDIM];     // codebook bf16
__device__ __half         g_dist[(size_t)NROWS * NB];  // approx distances
__device__ float  g_tmin[(size_t)NROWS * 16];   // per-row per-128-tile min
__device__ int    g_idx[NROWS];
__device__ int    g_cnt[NB];
__device__ int    g_bstart[NB + 1];
__device__ int    g_bcur[NB];
__device__ int    g_blist[NROWS];
__device__ float  g_cnorm[NB];
__device__ double g_loss;

__device__ __forceinline__ unsigned long long packKey(float s, unsigned j) {
    unsigned u = __float_as_uint(s);
    u = (u & 0x80000000u) ? ~u : (u | 0x80000000u);
    return ((unsigned long long)u << 32) | j;
}
__device__ __forceinline__ float unpackS(unsigned long long key) {
    unsigned u = (unsigned)(key >> 32);
    u = (u & 0x80000000u) ? (u & 0x7FFFFFFFu) : ~u;
    return __uint_as_float(u);
}
__device__ __forceinline__ uint32_t smem_u32(const void* p) {
    uint32_t a;
    asm("{ .reg .u64 t; cvta.to.shared.u64 t, %1; cvt.u32.u64 %0, t; }" : "=r"(a) : "l"(p));
    return a;
}
#define CP_ASYNC16(sm, gp) \
    asm volatile("cp.async.cg.shared.global [%0], [%1], 16;" :: "r"(sm), "l"(gp))
#define CP_COMMIT() asm volatile("cp.async.commit_group;")
#define CP_WAIT2()  asm volatile("cp.async.wait_group 2;")
#define LDMX4(r0, r1, r2, r3, addr)                                           \
    asm volatile("ldmatrix.sync.aligned.m8n8.x4.shared.b16 {%0,%1,%2,%3}, [%4];" \
                 : "=r"(r0), "=r"(r1), "=r"(r2), "=r"(r3) : "r"(addr))
#define MMA16816(d, a, b)                                                     \
    asm volatile("mma.sync.aligned.m16n8k16.row.col.f32.bf16.bf16.f32 "       \
                 "{%0,%1,%2,%3}, {%4,%5,%6,%7}, {%8,%9}, {%0,%1,%2,%3};"      \
                 : "+f"((d)[0]), "+f"((d)[1]), "+f"((d)[2]), "+f"((d)[3])     \
                 : "r"((a)[0]), "r"((a)[1]), "r"((a)[2]), "r"((a)[3]),        \
                   "r"((b)[0]), "r"((b)[1]))

// ---------------------------------------------------------------------------
__global__ void k_init() {
    int i = blockIdx.x * 256 + threadIdx.x;           // covers NB
    g_cnt[i] = 0;
    if (i == 0) g_loss = 0.0;
}

// fused: codebook row norms (exact fp32) + bf16 codebook copy
__global__ void k_cbprep(const float* __restrict__ cb) {
    int warp = blockIdx.x * 8 + (threadIdx.x >> 5);
    int lane = threadIdx.x & 31;
    const float* row = cb + (size_t)warp * CDIM;
    __nv_bfloat16* brow = g_cbb + (size_t)warp * CDIM;
    float s = 0.0f;
#pragma unroll
    for (int i = 0; i < CDIM / 32; i++) {
        float v = row[lane + i * 32];
        s += v * v;
        brow[lane + i * 32] = __float2bfloat16(v);
    }
#pragma unroll
    for (int o = 16; o > 0; o >>= 1) s += __shfl_xor_sync(0xFFFFFFFFu, s, o);
    if (lane == 0) g_cnorm[warp] = s;
}

// transpose x [img][c][t] -> x_flat [row][c], fp32 + bf16, float4 path
__global__ void k_split(const float* __restrict__ x) {
    __shared__ float tile[32][33];
    const int tid = threadIdx.x;
    const int tx = tid & 7, ty = tid >> 3;
    const int t0 = blockIdx.x * 32, c0 = blockIdx.y * 32, img = blockIdx.z;

    float4 g = *(const float4*)&x[((size_t)img * CDIM + c0 + ty) * TLEN + t0 + tx * 4];
    tile[tx * 4 + 0][ty] = g.x;
    tile[tx * 4 + 1][ty] = g.y;
    tile[tx * 4 + 2][ty] = g.z;
    tile[tx * 4 + 3][ty] = g.w;
    __syncthreads();

    float4 v;
    v.x = tile[ty][tx * 4 + 0];
    v.y = tile[ty][tx * 4 + 1];
    v.z = tile[ty][tx * 4 + 2];
    v.w = tile[ty][tx * 4 + 3];
    size_t o = ((size_t)img * TLEN + t0 + ty) * CDIM + c0 + tx * 4;
    *(float4*)&g_xf[o] = v;
    __nv_bfloat162 b0 = {__float2bfloat16(v.x), __float2bfloat16(v.y)};
    __nv_bfloat162 b1 = {__float2bfloat16(v.z), __float2bfloat16(v.w)};
    *(__nv_bfloat162*)&g_xb[o]     = b0;
    *(__nv_bfloat162*)&g_xb[o + 2] = b1;
}

// ---------------------------------------------------------------------------
// bf16 HMMA GEMM with ldmatrix + 4-stage cp.async pipeline.
// Writes g_dist (fp16) and g_tmin (fp32 per-row tile minima).
// ---------------------------------------------------------------------------
__global__ __launch_bounds__(256, 2)
void k_dist() {
    extern __shared__ char dsm[];
    __shared__ float cnS[128];
    __shared__ float tminS[2][128];

    const int tid = threadIdx.x;
    const int warp = tid >> 5, lane = tid & 31;
    const int wm = warp & 3, wn = warp >> 2;
    const int m0 = blockIdx.y * 128, j0 = blockIdx.x * 128;

    if (tid < 128) cnS[tid] = g_cnorm[j0 + tid];

    const int lr = tid >> 2, lq = tid & 3;
    auto issue = [&](int st, int kt) {
        char* base = dsm + st * STAGE_BYTES;
#pragma unroll
        for (int s = 0; s < 2; s++) {
            int r = lr + s * 64;
            uint32_t sa = smem_u32(base + r * 80 + lq * 16);
            uint32_t sb = smem_u32(base + 10240 + r * 80 + lq * 16);
            CP_ASYNC16(sa, &g_xb[(size_t)(m0 + r) * CDIM + kt + lq * 8]);
            CP_ASYNC16(sb, &g_cbb[(size_t)(j0 + r) * CDIM + kt + lq * 8]);
        }
        CP_COMMIT();
    };

    float acc[2][8][4];
#pragma unroll
    for (int mt = 0; mt < 2; mt++)
#pragma unroll
        for (int nt = 0; nt < 8; nt++)
#pragma unroll
            for (int e = 0; e < 4; e++) acc[mt][nt][e] = 0.0f;

    issue(0, 0); issue(1, 32); issue(2, 64);
    for (int ch = 0; ch < 16; ch++) {
        CP_WAIT2();
        __syncthreads();
        if (ch + 3 < 16) issue((ch + 3) & 3, (ch + 3) * 32);

        char* base = dsm + (ch & 3) * STAGE_BYTES;
        __nv_bfloat16 (*A)[40] = (__nv_bfloat16 (*)[40])base;
        __nv_bfloat16 (*B)[40] = (__nv_bfloat16 (*)[40])(base + 10240);
#pragma unroll
        for (int ks = 0; ks < 2; ks++) {
            uint32_t a[2][4], b[8][2];
#pragma unroll
            for (int mt = 0; mt < 2; mt++) {
                uint32_t ad = smem_u32(&A[wm * 32 + mt * 16 + (lane & 15)]
                                        [ks * 16 + (lane >> 4) * 8]);
                LDMX4(a[mt][0], a[mt][1], a[mt][2], a[mt][3], ad);
            }
#pragma unroll
            for (int p = 0; p < 4; p++) {
                int g = lane >> 3;
                uint32_t bd = smem_u32(&B[wn * 64 + p * 16 + (g >> 1) * 8 + (lane & 7)]
                                        [ks * 16 + (g & 1) * 8]);
                LDMX4(b[2 * p][0], b[2 * p][1], b[2 * p + 1][0], b[2 * p + 1][1], bd);
            }
#pragma unroll
            for (int mt = 0; mt < 2; mt++)
#pragma unroll
                for (int nt = 0; nt < 8; nt++)
                    MMA16816(acc[mt][nt], a[mt], b[nt]);
        }
    }

    // epilogue: s = cnorm - 2*dot -> g_dist (fp16) + per-row tile min
#pragma unroll
    for (int mt = 0; mt < 2; mt++) {
        float rmin0 = 1e30f, rmin1 = 1e30f;
#pragma unroll
        for (int nt = 0; nt < 8; nt++) {
            int rr = m0 + wm * 32 + mt * 16 + (lane >> 2);
            int cc = wn * 64 + nt * 8 + (lane & 3) * 2;
            float s0 = cnS[cc]     - 2.0f * acc[mt][nt][0];
            float s1 = cnS[cc + 1] - 2.0f * acc[mt][nt][1];
            float s2 = cnS[cc]     - 2.0f * acc[mt][nt][2];
            float s3 = cnS[cc + 1] - 2.0f * acc[mt][nt][3];
            *(__half2*)&g_dist[(size_t)rr * NB + j0 + cc]       = __floats2half2_rn(s0, s1);
            *(__half2*)&g_dist[(size_t)(rr + 8) * NB + j0 + cc] = __floats2half2_rn(s2, s3);
            rmin0 = fminf(rmin0, fminf(s0, s1));
            rmin1 = fminf(rmin1, fminf(s2, s3));
        }
        rmin0 = fminf(rmin0, __shfl_xor_sync(0xFFFFFFFFu, rmin0, 1));
        rmin0 = fminf(rmin0, __shfl_xor_sync(0xFFFFFFFFu, rmin0, 2));
        rmin1 = fminf(rmin1, __shfl_xor_sync(0xFFFFFFFFu, rmin1, 1));
        rmin1 = fminf(rmin1, __shfl_xor_sync(0xFFFFFFFFu, rmin1, 2));
        if ((lane & 3) == 0) {
            tminS[wn][wm * 32 + mt * 16 + (lane >> 2)]     = rmin0;
            tminS[wn][wm * 32 + mt * 16 + 8 + (lane >> 2)] = rmin1;
        }
    }
    __syncthreads();
    if (tid < 128)
        g_tmin[(size_t)(m0 + tid) * 16 + blockIdx.x] =
            fminf(tminS[0][tid], tminS[1][tid]);
}

// ---------------------------------------------------------------------------
// candidate scan (tile-min pruned) + exact fp32 rescore + count + loss.
// ---------------------------------------------------------------------------
__global__ __launch_bounds__(256)
void k_cand(const float* __restrict__ cb) {
    __shared__ float lred[8];
    const int warp = threadIdx.x >> 5, lane = threadIdx.x & 31;
    const int row = blockIdx.x * 8 + warp;

    float tm = g_tmin[(size_t)row * 16 + (lane & 15)];
    float mn = tm;
#pragma unroll
    for (int o = 16; o > 0; o >>= 1) mn = fminf(mn, __shfl_xor_sync(0xFFFFFFFFu, mn, o));
    const float thr = mn + MARGIN;

    const float* xr = g_xf + (size_t)row * CDIM;
    float xn = 0.0f;
#pragma unroll
    for (int qq = 0; qq < 16; qq++) {
        float xv = xr[lane + qq * 32];
        xn += xv * xv;
    }
#pragma unroll
    for (int o = 16; o > 0; o >>= 1) xn += __shfl_xor_sync(0xFFFFFFFFu, xn, o);

    unsigned long long best = 0xFFFFFFFFFFFFFFFFull;
#pragma unroll 1
    for (int t = 0; t < 16; t++) {
        float tmt = __shfl_sync(0xFFFFFFFFu, tm, t);
        if (tmt > thr) continue;
        const uint2* dp2 = (const uint2*)(g_dist + (size_t)row * NB + t * 128);
        uint2 v = dp2[lane];
        float2 fa = __half22float2(*(const __half2*)&v.x);
        float2 fb = __half22float2(*(const __half2*)&v.y);
        bool hit = fminf(fminf(fa.x, fa.y), fminf(fb.x, fb.y)) <= thr;
        unsigned m = __ballot_sync(0xFFFFFFFFu, hit);
        while (m) {
            int src = __ffs(m) - 1; m &= m - 1;
            unsigned vx = __shfl_sync(0xFFFFFFFFu, v.x, src);
            unsigned vy = __shfl_sync(0xFFFFFFFFu, v.y, src);
            int jb = t * 128 + src * 4;
            float2 ga = __half22float2(*(const __half2*)&vx);
            float2 gb = __half22float2(*(const __half2*)&vy);
            float gv[4] = {ga.x, ga.y, gb.x, gb.y};
#pragma unroll
            for (int q = 0; q < 4; q++) {
                if (gv[q] > thr) continue;
                int j = jb + q;
                const float* cr = cb + (size_t)j * CDIM;
                float d = 0.0f;
#pragma unroll
                for (int qq = 0; qq < 16; qq++)
                    d += xr[lane + qq * 32] * cr[lane + qq * 32];
#pragma unroll
                for (int o = 16; o > 0; o >>= 1) d += __shfl_xor_sync(0xFFFFFFFFu, d, o);
                float s = g_cnorm[j] - 2.0f * d;
                unsigned long long k = packKey(s, (unsigned)j);
                if (k < best) best = k;
            }
        }
    }
    if (lane == 0) {
        int idx = (int)(best & 0xFFFFFFFFu);
        g_idx[row] = idx;
        atomicAdd(&g_cnt[idx], 1);
        lred[warp] = xn + unpackS(best);
    }
    __syncthreads();
    if (threadIdx.x == 0) {
        float l = 0.0f;
#pragma unroll
        for (int i = 0; i < 8; i++) l += lred[i];
        atomicAdd(&g_loss, (double)l);
    }
}

// ---------------------------------------------------------------------------
// prefix scan over counts -> bucket offsets/cursors; fused perplexity
// ---------------------------------------------------------------------------
__global__ void k_prefix(float* __restrict__ out) {
    __shared__ int sh[1024];
    __shared__ double pr[1024];
    const int t = threadIdx.x;
    int c0 = g_cnt[2 * t], c1 = g_cnt[2 * t + 1];
    sh[t] = c0 + c1;
    {
        float p0 = (float)c0 / (32768.0f + 1e-10f);
        float p1 = (float)c1 / (32768.0f + 1e-10f);
        pr[t] = (double)(p0 * logf(p0 + 1e-7f)) + (double)(p1 * logf(p1 + 1e-7f));
    }
    __syncthreads();
#pragma unroll
    for (int o = 1; o < 1024; o <<= 1) {
        int add = (t >= o) ? sh[t - o] : 0;
        __syncthreads();
        sh[t] += add;
        __syncthreads();
    }
    int excl = (t == 0) ? 0 : sh[t - 1];
    g_bstart[2 * t]     = excl;
    g_bstart[2 * t + 1] = excl + c0;
    g_bcur[2 * t]       = excl;
    g_bcur[2 * t + 1]   = excl + c0;
    if (t == 1023) g_bstart[2048] = sh[1023];
    for (int o = 512; o > 0; o >>= 1) {
        if (t < o) pr[t] += pr[t + o];
        __syncthreads();
    }
    if (t == 0) out[OFF_PERP] = (float)exp(-pr[0]);
}

__global__ void k_fill() {
    int row = blockIdx.x * 256 + threadIdx.x;
    int idx = g_idx[row];
    int pos = atomicAdd(&g_bcur[idx], 1);
    g_blist[pos] = row;
}

// x_d_out gather-write only (transposed layout)
__global__ void k_out(const float* __restrict__ cb, float* __restrict__ out) {
    __shared__ int sidx[32];
    const int tid = threadIdx.x;
    const int r0 = blockIdx.x * 32;
    const int cbase = blockIdx.y * 128;
    const int img = r0 >> 10, t0 = r0 & 1023;

    if (tid < 32) sidx[tid] = g_idx[r0 + tid];
    __syncthreads();

    const int tt = tid & 31;
    const int c0 = cbase + (tid >> 5);
    const int idx = sidx[tt];
    const float* cbrow = cb + (size_t)idx * CDIM;
#pragma unroll
    for (int ci = 0; ci < 16; ci++) {
        int c = c0 + ci * 8;
        out[((size_t)img * CDIM + c) * TLEN + t0 + tt] = cbrow[c];
    }
}

// per-code segment sum (bucket gather) + EMA + reset; block 0 writes loss
__global__ __launch_bounds__(256)
void k_sum(const float* __restrict__ cs_in, const float* __restrict__ cc_in,
           float* __restrict__ sumR, float* __restrict__ cntR,
           float* __restrict__ ncb, float* __restrict__ out) {
    const int j = blockIdx.x;
    const int tid = threadIdx.x;
    const int s = g_bstart[j], e = g_bstart[j + 1];

    float a0 = 0.0f, a1 = 0.0f;
    for (int i = s; i < e; i++) {
        const float* xr = g_xf + (size_t)g_blist[i] * CDIM;
        a0 += xr[tid];
        a1 += xr[tid + 256];
    }
    float cnt = (float)(e - s);
    float cema = 0.99f * cc_in[j] + 0.01f * cnt;
    bool usage = (cema >= 1.0f);
    float denom = fmaxf(cema, 1e-10f);
    const float* xj = g_xf + (size_t)j * CDIM;

    float sema0 = 0.99f * cs_in[(size_t)j * CDIM + tid]       + 0.01f * a0;
    float sema1 = 0.99f * cs_in[(size_t)j * CDIM + tid + 256] + 0.01f * a1;
    sumR[(size_t)j * CDIM + tid]       = sema0;
    sumR[(size_t)j * CDIM + tid + 256] = sema1;
    ncb[(size_t)j * CDIM + tid]       = usage ? (sema0 / denom) : xj[tid];
    ncb[(size_t)j * CDIM + tid + 256] = usage ? (sema1 / denom) : xj[tid + 256];
    if (tid == 0) {
        cntR[j] = cema;
        if (j == 0) out[OFF_LOSS] = (float)(g_loss / (double)((size_t)NROWS * CDIM));
    }
}

// ---------------------------------------------------------------------------
extern "C" void kernel_launch(void* const* d_in, const int* in_sizes, int n_in,
                              void* d_out, int out_size) {
    const float* x  = (const float*)d_in[0];
    const float* cb = (const float*)d_in[1];
    const float* cs = (const float*)d_in[2];
    const float* cc = (const float*)d_in[3];
    float* out  = (float*)d_out;
    float* ncb  = out + OFF_NCB;
    float* sumR = out + OFF_SUM;
    float* cntR = out + OFF_CNT;

    cudaFuncSetAttribute(k_dist, cudaFuncAttributeMaxDynamicSharedMemorySize, DSMEM);

    k_init<<<NB / 256, 256>>>();
    k_cbprep<<<NB / 8, 256>>>(cb);
    k_split<<<dim3(TLEN / 32, CDIM / 32, NIMG), 256>>>(x);
    k_dist<<<dim3(NB / 128, NROWS / 128), 256, DSMEM>>>();
    k_cand<<<NROWS / 8, 256>>>(cb);
    k_prefix<<<1, 1024>>>(out);
    k_fill<<<NROWS / 256, 256>>>();
    dim3 go(NROWS / 32, CDIM / 128);
    k_out<<<go, 256>>>(cb, out);
    k_sum<<<NB, 256>>>(cs, cc, sumR, cntR, ncb, out);
}